// round 3
// baseline (speedup 1.0000x reference)
#include <cuda_runtime.h>
#include <math.h>
#include <stdint.h>

#define H     128
#define NB    16384
#define NPG   26
#define EPG   52
#define NCL   7
#define NTOT  (NB*NPG)      // 425984
#define NEDGE (NB*EPG)      // 851968
#define PITCH 132           // smem row pitch (words) — kills bank conflicts

// ------------- scratch: device globals (no runtime allocation) -------------
__device__ float g_hp[NB*32*H];      // node features, padded 32 rows/graph
__device__ float g_x2[NB*NCL*H];     // pooled cluster features (in-place)
__device__ float g_pm[NB*H];         // per-graph mean of clusters
__device__ float g_linkpart[NB];
__device__ float g_entpart[NB];

// ============ K1: atom encoder (emb column-slice resident in smem) ============
// grid (256, 4), 256 threads. Block = 64 graphs x 32-column slice.
__global__ void k_encode(const int* __restrict__ x, const float* __restrict__ emb) {
    extern __shared__ float s_emb[];            // 9*119*32 floats
    const int cg   = blockIdx.y;
    const int lane = threadIdx.x & 31;
    const int sub  = threadIdx.x >> 5;
    for (int i = threadIdx.x; i < 9*119*32; i += 256)
        s_emb[i] = emb[(size_t)(i >> 5) * 128 + cg*32 + (i & 31)];
    __syncthreads();
    const int g0 = blockIdx.x * 64;
    for (int q = 0; q < 64; q++) {
        const int g = g0 + q;
        for (int i = sub; i < 26; i += 8) {
            const int n = g*26 + i;
            float acc = 0.f;
            #pragma unroll
            for (int f = 0; f < 9; f++) {
                int v = __ldg(&x[(size_t)n*9 + f]);
                acc += s_emb[(f*119 + v)*32 + lane];
            }
            g_hp[(size_t)(g*32 + i)*128 + cg*32 + lane] = acc;
        }
        // zero pad rows 26..31 (keeps everything deterministic)
        if (sub < 6)
            g_hp[(size_t)(g*32 + 26 + sub)*128 + cg*32 + lane] = 0.f;
    }
}

// ============ tf32 mma.sync helper ============
__device__ __forceinline__ void mma_tf32(float* d, const uint32_t* a,
                                         uint32_t b0, uint32_t b1) {
    asm volatile(
        "mma.sync.aligned.m16n8k8.row.col.f32.tf32.tf32.f32 "
        "{%0,%1,%2,%3}, {%4,%5,%6,%7}, {%8,%9}, {%0,%1,%2,%3};\n"
        : "+f"(d[0]), "+f"(d[1]), "+f"(d[2]), "+f"(d[3])
        : "r"(a[0]), "r"(a[1]), "r"(a[2]), "r"(a[3]), "r"(b0), "r"(b1));
}

// One K=128 GEMM phase: D += sA[128 x 128] @ sW[128 x 128]
// Warp tiling: 8 warps = 4(M) x 2(N); warp tile 32x64; mma m16n8k8.
__device__ __forceinline__ void gemm_phase(const float* __restrict__ sA,
                                           const float* __restrict__ sW,
                                           float d[2][8][4],
                                           int wr0, int wc0, int gid, int tig)
{
    #pragma unroll 4
    for (int ks = 0; ks < 16; ks++) {
        const int kk = ks * 8;
        uint32_t a[2][4];
        #pragma unroll
        for (int mi = 0; mi < 2; mi++) {
            const float* ap = sA + (wr0 + mi*16 + gid)*PITCH + kk + tig;
            a[mi][0] = __float_as_uint(ap[0]);
            a[mi][1] = __float_as_uint(ap[8*PITCH]);
            a[mi][2] = __float_as_uint(ap[4]);
            a[mi][3] = __float_as_uint(ap[8*PITCH + 4]);
        }
        const float* bp = sW + (kk + tig)*PITCH + wc0 + gid;
        #pragma unroll
        for (int nj = 0; nj < 8; nj++) {
            uint32_t b0 = __float_as_uint(bp[nj*8]);
            uint32_t b1 = __float_as_uint(bp[nj*8 + 4*PITCH]);
            mma_tf32(d[0][nj], a[0], b0, b1);
            mma_tf32(d[1][nj], a[1], b0, b1);
        }
    }
}

// ============ K2: fused layer kernel ============
// POOLED=0: block = 4 graphs (128 padded rows). Computes neighbor mean in smem,
//           then Out = bn([mean||h] @ [Wl;Wr] + bl) (+relu) + h, in place on g_hp.
// POOLED=1: block = 128 rows of g_x2; mean operand is g_pm[row/7]; no relu.
template<int RELU, int POOLED>
__global__ __launch_bounds__(256)
void k_layer(const int* __restrict__ ei,
             const float* __restrict__ Wl, const float* __restrict__ Wr,
             const float* __restrict__ bl,
             const float* __restrict__ bng, const float* __restrict__ bnb,
             const float* __restrict__ bnm, const float* __restrict__ bnv)
{
    extern __shared__ float smem[];
    float* sH = smem;                     // 128 x PITCH  (h rows; residual source)
    float* sM = sH + 128*PITCH;           // 128 x PITCH  (mean rows)
    float* sW = sM + 128*PITCH;           // 128 x PITCH  (weights, reused Wl->Wr)
    __shared__ int   sse[4*EPG], sde[4*EPG];
    __shared__ int   sdeg[128];
    __shared__ float sscale[128], sshift[128];

    const int tid = threadIdx.x;
    float* Aout = POOLED ? (g_x2 + (size_t)blockIdx.x*128*H)
                         : (g_hp + (size_t)blockIdx.x*128*H);

    if (!POOLED) {
        for (int i = tid; i < 128*32; i += 256) {
            int r = i >> 5, c = (i & 31) * 4;
            *(float4*)&sH[r*PITCH + c] = *(const float4*)(Aout + (size_t)r*H + c);
            *(float4*)&sM[r*PITCH + c] = make_float4(0.f, 0.f, 0.f, 0.f);
        }
        const int g0 = blockIdx.x * 4;
        if (tid < 4*EPG) {
            int q = tid / EPG, e = tid - q*EPG;
            int g = g0 + q;
            sse[tid] = ei[(size_t)g*EPG + e]                 - g*NPG;
            sde[tid] = ei[(size_t)NEDGE + (size_t)g*EPG + e] - g*NPG;
        }
        if (tid < 128) sdeg[tid] = 0;
    } else {
        const int row0 = blockIdx.x * 128;
        for (int i = tid; i < 128*32; i += 256) {
            int r = i >> 5, c = (i & 31) * 4;
            *(float4*)&sH[r*PITCH + c] = *(const float4*)(g_x2 + (size_t)(row0 + r)*H + c);
            *(float4*)&sM[r*PITCH + c] = *(const float4*)(g_pm + (size_t)((row0 + r)/7)*H + c);
        }
    }
    for (int i = tid; i < 128*32; i += 256) {
        int r = i >> 5, c = (i & 31) * 4;
        *(float4*)&sW[r*PITCH + c] = *(const float4*)(Wl + (size_t)r*H + c);
    }
    if (tid < 128) {
        float sc = bng[tid] * rsqrtf(bnv[tid] + 1e-5f);
        sscale[tid] = sc;
        sshift[tid] = bnb[tid] + sc * (bl[tid] - bnm[tid]);
    }
    __syncthreads();

    if (!POOLED) {
        if (tid < 4*EPG) atomicAdd(&sdeg[(tid/EPG)*32 + sde[tid]], 1);
        __syncthreads();
        // mean: thread owns (graph q, columns c, c+64) -> race-free
        const int q = tid >> 6, c = tid & 63;
        const int* se = sse + q*EPG;
        const int* de = sde + q*EPG;
        #pragma unroll 4
        for (int e = 0; e < EPG; e++) {
            int sr = (q*32 + se[e])*PITCH + c;
            int dr = (q*32 + de[e])*PITCH + c;
            sM[dr]      += sH[sr];
            sM[dr + 64] += sH[sr + 64];
        }
        for (int n = 0; n < 32; n++) {
            float r = 1.f / fmaxf((float)sdeg[q*32 + n], 1.f);
            sM[(q*32 + n)*PITCH + c]      *= r;
            sM[(q*32 + n)*PITCH + c + 64] *= r;
        }
        __syncthreads();
    }

    const int lane = tid & 31, warp = tid >> 5;
    const int gid = lane >> 2, tig = lane & 3;
    const int wr0 = (warp & 3) * 32;
    const int wc0 = (warp >> 2) * 64;
    float d[2][8][4] = {};

    gemm_phase(sM, sW, d, wr0, wc0, gid, tig);      // mean @ Wl
    __syncthreads();
    for (int i = tid; i < 128*32; i += 256) {
        int r = i >> 5, c = (i & 31) * 4;
        *(float4*)&sW[r*PITCH + c] = *(const float4*)(Wr + (size_t)r*H + c);
    }
    __syncthreads();
    gemm_phase(sH, sW, d, wr0, wc0, gid, tig);      // h @ Wr

    // epilogue: bn + (relu) + residual, in-place write
    #pragma unroll
    for (int mi = 0; mi < 2; mi++)
        #pragma unroll
        for (int half = 0; half < 2; half++) {
            const int row = wr0 + mi*16 + gid + half*8;
            #pragma unroll
            for (int nj = 0; nj < 8; nj++) {
                const int col = wc0 + nj*8 + tig*2;
                float v0 = d[mi][nj][half*2 + 0] * sscale[col]     + sshift[col];
                float v1 = d[mi][nj][half*2 + 1] * sscale[col + 1] + sshift[col + 1];
                if (RELU) { v0 = fmaxf(v0, 0.f); v1 = fmaxf(v1, 0.f); }
                v0 += sH[row*PITCH + col];
                v1 += sH[row*PITCH + col + 1];
                *(float2*)(Aout + (size_t)row*H + col) = make_float2(v0, v1);
            }
        }
}

// ============ K3: fused final aggregation + assignment + softmax + pool + losses ============
// grid NB, 128 threads (thread = feature column)
__global__ void k_fin(const int* __restrict__ ei,
                      const float* __restrict__ aWl, const float* __restrict__ abl,
                      const float* __restrict__ aWr)
{
    __shared__ float fH[NPG*H];
    __shared__ float fM[NPG*H];
    __shared__ float sWl[H*NCL], sWr[H*NCL];
    __shared__ float ssl[NPG*NCL];
    __shared__ float sd [NPG*NCL];
    __shared__ float adj[NPG*NPG];
    __shared__ int   se[EPG], de[EPG];
    __shared__ int   degi[NPG];
    __shared__ float red[128], red2[128];
    const int g = blockIdx.x, tid = threadIdx.x;
    const float* hg = g_hp + (size_t)g*32*H;       // rows 0..25 contiguous
    for (int i = tid; i < NPG*H; i += 128) { fH[i] = hg[i]; fM[i] = 0.f; }
    for (int i = tid; i < H*NCL; i += 128) { sWl[i] = aWl[i]; sWr[i] = aWr[i]; }
    for (int i = tid; i < NPG*NPG; i += 128) adj[i] = 0.f;
    if (tid < EPG) {
        se[tid] = ei[(size_t)g*EPG + tid]                 - g*NPG;
        de[tid] = ei[(size_t)NEDGE + (size_t)g*EPG + tid] - g*NPG;
    }
    if (tid < NPG) degi[tid] = 0;
    __syncthreads();
    if (tid < EPG) atomicAdd(&degi[de[tid]], 1);
    __syncthreads();
    for (int e = 0; e < EPG; e++)
        fM[de[e]*H + tid] += fH[se[e]*H + tid];
    __syncthreads();
    for (int n = 0; n < NPG; n++)
        fM[n*H + tid] *= 1.f / fmaxf((float)degi[n], 1.f);
    __syncthreads();
    // assignment logits
    for (int idx = tid; idx < NPG*NCL; idx += 128) {
        int n = idx / NCL, c = idx - n*NCL;
        float p = abl[c];
        for (int k = 0; k < H; k++)
            p += fM[n*H + k]*sWl[k*NCL + c] + fH[n*H + k]*sWr[k*NCL + c];
        ssl[idx] = p;
    }
    __syncthreads();
    float ent_local = 0.f;
    if (tid < NPG) {
        float v[NCL], mx = -1e30f;
        #pragma unroll
        for (int c = 0; c < NCL; c++) { v[c] = ssl[tid*NCL + c]; mx = fmaxf(mx, v[c]); }
        float s = 0.f;
        #pragma unroll
        for (int c = 0; c < NCL; c++) { v[c] = expf(v[c] - mx); s += v[c]; }
        float inv = 1.f / s;
        #pragma unroll
        for (int c = 0; c < NCL; c++) {
            float p = v[c] * inv;
            sd[tid*NCL + c] = p;
            ent_local += -p * logf(p + 1e-15f);
        }
    }
    if (tid < EPG) atomicAdd(&adj[se[tid]*NPG + de[tid]], 1.f);
    __syncthreads();
    float* x2g = g_x2 + (size_t)g*NCL*H;
    #pragma unroll
    for (int c = 0; c < NCL; c++) {
        float a = 0.f;
        #pragma unroll
        for (int n = 0; n < NPG; n++) a += sd[n*NCL + c] * fH[n*H + tid];
        x2g[c*H + tid] = a;
    }
    float link_local = 0.f;
    for (int p = tid; p < NPG*NPG; p += 128) {
        int n = p / NPG, m = p - NPG*n;
        float ss = 0.f;
        #pragma unroll
        for (int c = 0; c < NCL; c++) ss += sd[n*NCL + c] * sd[m*NCL + c];
        float dd = adj[p] - ss;
        link_local += dd * dd;
    }
    red[tid] = link_local; red2[tid] = ent_local;
    __syncthreads();
    for (int s = 64; s > 0; s >>= 1) {
        if (tid < s) { red[tid] += red[tid + s]; red2[tid] += red2[tid + s]; }
        __syncthreads();
    }
    if (tid == 0) { g_linkpart[g] = red[0]; g_entpart[g] = red2[0]; }
}

// ============ K4: per-graph mean of clusters ============
__global__ void k_pmean() {
    int idx = blockIdx.x * 256 + threadIdx.x;
    int g = idx >> 7, col = idx & 127;
    const float* xg = g_x2 + (size_t)g*NCL*H + col;
    float a = 0.f;
    #pragma unroll
    for (int c = 0; c < NCL; c++) a += xg[c*H];
    g_pm[idx] = a * (1.f/7.f);
}

// ============ K5: readout ============
__global__ void k_readout(const float* __restrict__ linW, const float* __restrict__ linb,
                          float* __restrict__ out) {
    const int g = blockIdx.x, tid = threadIdx.x;   // 128
    const float* xg = g_x2 + (size_t)g*NCL*H;
    float v = 0.f;
    #pragma unroll
    for (int c = 0; c < NCL; c++) v += xg[c*H + tid];
    v *= (1.f/7.f);
    __shared__ float red[128];
    red[tid] = v * linW[tid];
    __syncthreads();
    for (int s = 64; s > 0; s >>= 1) {
        if (tid < s) red[tid] += red[tid + s];
        __syncthreads();
    }
    if (tid == 0) out[g] = 1.f / (1.f + expf(-(red[0] + linb[0])));
}

// ============ K6: deterministic loss reduction ============
__global__ void k_reduce(float* __restrict__ out) {
    __shared__ float s1[1024], s2[1024];
    const int tid = threadIdx.x;
    float a = 0.f, b = 0.f;
    for (int i = tid; i < NB; i += 1024) { a += g_linkpart[i]; b += g_entpart[i]; }
    s1[tid] = a; s2[tid] = b;
    __syncthreads();
    for (int s = 512; s > 0; s >>= 1) {
        if (tid < s) { s1[tid] += s1[tid + s]; s2[tid] += s2[tid + s]; }
        __syncthreads();
    }
    if (tid == 0) {
        out[NB]     = sqrtf(s1[0]) / 11075584.f;   // nb * 26 * 26
        out[NB + 1] = s2[0] / (float)NTOT;
    }
}

extern "C" void kernel_launch(void* const* d_in, const int* in_sizes, int n_in,
                              void* d_out, int out_size) {
    (void)in_sizes; (void)n_in; (void)out_size;
    const int*   x    = (const int*)  d_in[0];
    const int*   ei   = (const int*)  d_in[1];
    const float* emb  = (const float*)d_in[3];
    const float* cWl  = (const float*)d_in[4];
    const float* cbl  = (const float*)d_in[5];
    const float* cWr  = (const float*)d_in[6];
    const float* bng  = (const float*)d_in[7];
    const float* bnb  = (const float*)d_in[8];
    const float* bnm  = (const float*)d_in[9];
    const float* bnv  = (const float*)d_in[10];
    const float* aWl  = (const float*)d_in[11];
    const float* abl  = (const float*)d_in[12];
    const float* aWr  = (const float*)d_in[13];
    const float* linW = (const float*)d_in[14];
    const float* linb = (const float*)d_in[15];
    float* out = (float*)d_out;

    const int enc_smem   = 9*119*32*4;           // 137088
    const int layer_smem = 3*128*PITCH*4;        // 202752
    cudaFuncSetAttribute(k_encode, cudaFuncAttributeMaxDynamicSharedMemorySize, enc_smem);
    cudaFuncSetAttribute(k_layer<1,0>, cudaFuncAttributeMaxDynamicSharedMemorySize, layer_smem);
    cudaFuncSetAttribute(k_layer<0,1>, cudaFuncAttributeMaxDynamicSharedMemorySize, layer_smem);

    k_encode<<<dim3(256, 4), 256, enc_smem>>>(x, emb);

    for (int li = 0; li < 2; li++) {
        k_layer<1,0><<<NB/4, 256, layer_smem>>>(ei,
            cWl + li*16384, cWr + li*16384, cbl + li*128,
            bng + li*128, bnb + li*128, bnm + li*128, bnv + li*128);
    }

    k_fin<<<NB, 128>>>(ei, aWl, abl, aWr);

    for (int li = 2; li < 4; li++) {
        k_pmean<<<NB*128/256, 256>>>();
        k_layer<0,1><<<NB*NCL/128, 256, layer_smem>>>(ei,
            cWl + li*16384, cWr + li*16384, cbl + li*128,
            bng + li*128, bnb + li*128, bnm + li*128, bnv + li*128);
    }

    k_readout<<<NB, 128>>>(linW, linb, out);
    k_reduce<<<1, 1024>>>(out);
}

// round 4
// speedup vs baseline: 1.7754x; 1.7754x over previous
#include <cuda_runtime.h>
#include <math.h>
#include <stdint.h>

#define H     128
#define NB    16384
#define NPG   26
#define EPG   52
#define NCL   7
#define NTOT  (NB*NPG)      // 425984
#define NEDGE (NB*EPG)      // 851968

// ------------- scratch: device globals (no runtime allocation) -------------
__device__ float g_h[NTOT*H];        // node features (in-place per layer)
__device__ float g_mean[NTOT*H];     // neighbor means
__device__ float g_slog[NTOT*NCL];   // assignment logits
__device__ float g_x2[NB*NCL*H];     // pooled cluster features (in-place)
__device__ float g_pm[NB*H];         // per-graph mean of clusters
__device__ float g_linkpart[NB];
__device__ float g_entpart[NB];

// ================= K1: atom encoder =================
__global__ void k_encode(const int* __restrict__ x, const float* __restrict__ emb) {
    const int tid = threadIdx.x;
    const int n0  = blockIdx.x * 32;
    __shared__ int sx[32 * 9];
    for (int i = tid; i < 32 * 9; i += 128) sx[i] = x[(size_t)n0 * 9 + i];
    __syncthreads();
    for (int nn = 0; nn < 32; nn++) {
        float acc = 0.f;
        #pragma unroll
        for (int f = 0; f < 9; f++) {
            int v = sx[nn * 9 + f];
            acc += emb[((size_t)f * 119 + v) * 128 + tid];
        }
        g_h[(size_t)(n0 + nn) * 128 + tid] = acc;
    }
}

// ================= K2: neighbor-mean aggregation (4 graphs/block) =================
__global__ __launch_bounds__(256)
void k_agg(const int* __restrict__ ei) {
    extern __shared__ float smem[];
    float* sh  = smem;                 // 4*26*128
    float* sag = smem + 4*26*128;      // 4*26*128
    __shared__ int   sse[4*EPG], sde[4*EPG];
    __shared__ int   degi[4*NPG];
    __shared__ float rdeg[4*NPG];
    const int tid = threadIdx.x;
    const int g0  = blockIdx.x * 4;
    const float* src = g_h + (size_t)g0 * NPG * H;
    // linear cooperative load of 4 contiguous graphs (13312 floats)
    for (int i = tid; i < 4*NPG*32; i += 256) {
        *(float4*)&sh[i*4]  = *(const float4*)(src + (size_t)i*4);
        *(float4*)&sag[i*4] = make_float4(0.f,0.f,0.f,0.f);
    }
    if (tid < 4*EPG) {
        int q = tid / EPG, e = tid - q*EPG, g = g0 + q;
        sse[tid] = ei[(size_t)g*EPG + e]                 - g*NPG;
        sde[tid] = ei[(size_t)NEDGE + (size_t)g*EPG + e] - g*NPG;
    }
    if (tid < 4*NPG) degi[tid] = 0;
    __syncthreads();
    if (tid < 4*EPG) atomicAdd(&degi[(tid/EPG)*NPG + sde[tid]], 1);
    __syncthreads();
    if (tid < 4*NPG) rdeg[tid] = 1.f / fmaxf((float)degi[tid], 1.f);
    // thread owns (graph q, float2 columns c,c+1) -> race-free accumulation
    const int q = tid >> 6;
    const int c = (tid & 63) * 2;
    const int* se = sse + q*EPG;
    const int* de = sde + q*EPG;
    float* shq  = sh  + q*NPG*H + c;
    float* sagq = sag + q*NPG*H + c;
    #pragma unroll 4
    for (int e = 0; e < EPG; e++) {
        float2 s = *(float2*)(shq + se[e]*H);
        float2* d = (float2*)(sagq + de[e]*H);
        float2 dv = *d;
        dv.x += s.x; dv.y += s.y;
        *d = dv;
    }
    __syncthreads();
    float* dst = g_mean + ((size_t)g0 + q) * NPG * H + c;
    #pragma unroll
    for (int n = 0; n < NPG; n++) {
        float r = rdeg[q*NPG + n];
        float2 v = *(float2*)(sagq + n*H);
        v.x *= r; v.y *= r;
        *(float2*)(dst + (size_t)n*H) = v;
    }
}

// ================= tf32 mma.sync helper (verified layout) =================
__device__ __forceinline__ void mma_tf32(float* d, const uint32_t* a,
                                         uint32_t b0, uint32_t b1) {
    asm volatile(
        "mma.sync.aligned.m16n8k8.row.col.f32.tf32.tf32.f32 "
        "{%0,%1,%2,%3}, {%4,%5,%6,%7}, {%8,%9}, {%0,%1,%2,%3};\n"
        : "+f"(d[0]), "+f"(d[1]), "+f"(d[2]), "+f"(d[3])
        : "r"(a[0]), "r"(a[1]), "r"(a[2]), "r"(a[3]), "r"(b0), "r"(b1));
}

#define WPITCH 132
#define APITCH 68

// ================= K3: tensor-core GEMM + bias/BN/(ReLU)/residual, in place =================
// Out = bn([mean||h] @ [Wl;Wr] + bl)(+relu) + h
// POOLED=0: mean=g_mean, h=g_h, both row-indexed by global row.
// POOLED=1: mean=g_pm[row/7], h=g_x2.
template<int RELU, int POOLED>
__global__ __launch_bounds__(256)
void k_gemm_tc(const float* __restrict__ Wl, const float* __restrict__ Wr,
               const float* __restrict__ bl,
               const float* __restrict__ bng, const float* __restrict__ bnb,
               const float* __restrict__ bnm, const float* __restrict__ bnv)
{
    extern __shared__ float smem[];
    float* sW = smem;                  // 128 x WPITCH
    float* sA = smem + 128*WPITCH;     // 128 x APITCH (64-wide k chunk)
    __shared__ float sscale[128], sshift[128];

    const int tid  = threadIdx.x;
    const int row0 = blockIdx.x * 128;
    const float* Am = POOLED ? g_pm : g_mean;
    float*       Ah = POOLED ? g_x2 : g_h;

    if (tid < 128) {
        float sc = bng[tid] * rsqrtf(bnv[tid] + 1e-5f);
        sscale[tid] = sc;
        sshift[tid] = bnb[tid] + sc * (bl[tid] - bnm[tid]);
    }

    const int lane = tid & 31, warp = tid >> 5;
    const int gid = lane >> 2, tig = lane & 3;
    const int wr0 = (warp & 3) * 32;
    const int wc0 = (warp >> 2) * 64;
    float d[2][8][4] = {};

    #pragma unroll
    for (int phase = 0; phase < 2; phase++) {
        const float* Wop = phase == 0 ? Wl : Wr;
        __syncthreads();   // previous phase done reading sW
        for (int i = tid; i < 128*32; i += 256) {
            int r = i >> 5, c = (i & 31) * 4;
            *(float4*)&sW[r*WPITCH + c] = *(const float4*)(Wop + (size_t)r*128 + c);
        }
        #pragma unroll
        for (int kc = 0; kc < 2; kc++) {
            __syncthreads();   // previous chunk done reading sA (also orders sW load)
            for (int i = tid; i < 128*16; i += 256) {
                int r = i >> 4, c = (i & 15) * 4;
                int grow = row0 + r;
                const float* ap;
                if (phase == 0) {
                    int mrow = POOLED ? (grow / 7) : grow;
                    ap = Am + (size_t)mrow * 128;
                } else {
                    ap = Ah + (size_t)grow * 128;
                }
                *(float4*)&sA[r*APITCH + c] = *(const float4*)(ap + kc*64 + c);
            }
            __syncthreads();
            #pragma unroll
            for (int ks = 0; ks < 8; ks++) {
                const int kk = ks * 8;
                uint32_t a[2][4];
                #pragma unroll
                for (int mi = 0; mi < 2; mi++) {
                    const float* ap = sA + (wr0 + mi*16 + gid)*APITCH + kk + tig;
                    a[mi][0] = __float_as_uint(ap[0]);
                    a[mi][1] = __float_as_uint(ap[8*APITCH]);
                    a[mi][2] = __float_as_uint(ap[4]);
                    a[mi][3] = __float_as_uint(ap[8*APITCH + 4]);
                }
                const float* bp = sW + (kc*64 + kk + tig)*WPITCH + wc0 + gid;
                #pragma unroll
                for (int nj = 0; nj < 8; nj++) {
                    uint32_t b0 = __float_as_uint(bp[nj*8]);
                    uint32_t b1 = __float_as_uint(bp[nj*8 + 4*WPITCH]);
                    mma_tf32(d[0][nj], a[0], b0, b1);
                    mma_tf32(d[1][nj], a[1], b0, b1);
                }
            }
        }
    }

    // epilogue: bn + (relu) + residual (re-read from global), in-place write
    #pragma unroll
    for (int mi = 0; mi < 2; mi++)
        #pragma unroll
        for (int half = 0; half < 2; half++) {
            const int row = wr0 + mi*16 + gid + half*8;
            float* orow = Ah + (size_t)(row0 + row) * 128;
            #pragma unroll
            for (int nj = 0; nj < 8; nj++) {
                const int col = wc0 + nj*8 + tig*2;
                float2 res = *(float2*)(orow + col);
                float v0 = d[mi][nj][half*2 + 0] * sscale[col]     + sshift[col];
                float v1 = d[mi][nj][half*2 + 1] * sscale[col + 1] + sshift[col + 1];
                if (RELU) { v0 = fmaxf(v0, 0.f); v1 = fmaxf(v1, 0.f); }
                *(float2*)(orow + col) = make_float2(v0 + res.x, v1 + res.y);
            }
        }
}

// ================= K4: assignment logits (warp per node) =================
__global__ void k_slog(const float* __restrict__ aWl, const float* __restrict__ abl,
                       const float* __restrict__ aWr) {
    __shared__ float sWl[128 * NCL], sWr[128 * NCL];
    const int tid = threadIdx.x;  // 256
    for (int i = tid; i < 128 * NCL; i += 256) { sWl[i] = aWl[i]; sWr[i] = aWr[i]; }
    __syncthreads();
    const int warp = tid >> 5, lane = tid & 31;
    const int gw = blockIdx.x * 8 + warp;
    const int stride = gridDim.x * 8;
    for (int n = gw; n < NTOT; n += stride) {
        const float* mrow = g_mean + (size_t)n * 128;
        const float* hrow = g_h    + (size_t)n * 128;
        float m[4], h[4];
        #pragma unroll
        for (int j = 0; j < 4; j++) { m[j] = mrow[lane + 32*j]; h[j] = hrow[lane + 32*j]; }
        #pragma unroll
        for (int c = 0; c < NCL; c++) {
            float p = 0.f;
            #pragma unroll
            for (int j = 0; j < 4; j++) {
                int k = lane + 32*j;
                p += m[j] * sWl[k*NCL + c] + h[j] * sWr[k*NCL + c];
            }
            #pragma unroll
            for (int off = 16; off > 0; off >>= 1)
                p += __shfl_down_sync(0xffffffffu, p, off);
            if (lane == 0) g_slog[(size_t)n*NCL + c] = p + abl[c];
        }
    }
}

// ================= K5: per-graph softmax + pooling + losses =================
__global__ void k_pool(const int* __restrict__ ei) {
    __shared__ float sh[NPG * H];
    __shared__ float sd[NPG * NCL];
    __shared__ float adj[NPG * NPG];
    __shared__ float red[128], red2[128];
    const int g = blockIdx.x, tid = threadIdx.x;  // 128
    const float* hg = g_h + (size_t)g * NPG * H;
    for (int i = tid; i < NPG * H; i += 128) sh[i] = hg[i];
    for (int i = tid; i < NPG * NPG; i += 128) adj[i] = 0.f;
    __syncthreads();
    float ent_local = 0.f;
    if (tid < NPG) {
        const float* sl = g_slog + ((size_t)g * NPG + tid) * NCL;
        float v[NCL];
        float mx = -1e30f;
        #pragma unroll
        for (int c = 0; c < NCL; c++) { v[c] = sl[c]; mx = fmaxf(mx, v[c]); }
        float s = 0.f;
        #pragma unroll
        for (int c = 0; c < NCL; c++) { v[c] = expf(v[c] - mx); s += v[c]; }
        float inv = 1.f / s;
        #pragma unroll
        for (int c = 0; c < NCL; c++) {
            float p = v[c] * inv;
            sd[tid * NCL + c] = p;
            ent_local += -p * logf(p + 1e-15f);
        }
    }
    if (tid < EPG) {
        int s = ei[(size_t)g * EPG + tid]         - g * NPG;
        int d = ei[(size_t)NEDGE + g * EPG + tid] - g * NPG;
        atomicAdd(&adj[s * NPG + d], 1.f);
    }
    __syncthreads();
    float* x2g = g_x2 + (size_t)g * NCL * H;
    #pragma unroll
    for (int c = 0; c < NCL; c++) {
        float a = 0.f;
        #pragma unroll
        for (int n = 0; n < NPG; n++) a += sd[n * NCL + c] * sh[n * 128 + tid];
        x2g[c * 128 + tid] = a;
    }
    float link_local = 0.f;
    for (int p = tid; p < NPG * NPG; p += 128) {
        int n = p / NPG, m = p - NPG * n;
        float ss = 0.f;
        #pragma unroll
        for (int c = 0; c < NCL; c++) ss += sd[n * NCL + c] * sd[m * NCL + c];
        float d = adj[p] - ss;
        link_local += d * d;
    }
    red[tid] = link_local; red2[tid] = ent_local;
    __syncthreads();
    for (int s = 64; s > 0; s >>= 1) {
        if (tid < s) { red[tid] += red[tid + s]; red2[tid] += red2[tid + s]; }
        __syncthreads();
    }
    if (tid == 0) { g_linkpart[g] = red[0]; g_entpart[g] = red2[0]; }
}

// ================= K6: per-graph mean of clusters =================
__global__ void k_pmean() {
    int idx = blockIdx.x * 256 + threadIdx.x;
    int g = idx >> 7, col = idx & 127;
    const float* xg = g_x2 + (size_t)g * NCL * H + col;
    float a = 0.f;
    #pragma unroll
    for (int c = 0; c < NCL; c++) a += xg[c * 128];
    g_pm[idx] = a * (1.f / 7.f);
}

// ================= K7: readout =================
__global__ void k_readout(const float* __restrict__ linW, const float* __restrict__ linb,
                          float* __restrict__ out) {
    const int g = blockIdx.x, tid = threadIdx.x;  // 128
    const float* xg = g_x2 + (size_t)g * NCL * H;
    float v = 0.f;
    #pragma unroll
    for (int c = 0; c < NCL; c++) v += xg[c * 128 + tid];
    v *= (1.f / 7.f);
    __shared__ float red[128];
    red[tid] = v * linW[tid];
    __syncthreads();
    for (int s = 64; s > 0; s >>= 1) {
        if (tid < s) red[tid] += red[tid + s];
        __syncthreads();
    }
    if (tid == 0) out[g] = 1.f / (1.f + expf(-(red[0] + linb[0])));
}

// ================= K8: deterministic loss reduction =================
__global__ void k_reduce(float* __restrict__ out) {
    __shared__ float s1[1024], s2[1024];
    const int tid = threadIdx.x;
    float a = 0.f, b = 0.f;
    for (int i = tid; i < NB; i += 1024) { a += g_linkpart[i]; b += g_entpart[i]; }
    s1[tid] = a; s2[tid] = b;
    __syncthreads();
    for (int s = 512; s > 0; s >>= 1) {
        if (tid < s) { s1[tid] += s1[tid + s]; s2[tid] += s2[tid + s]; }
        __syncthreads();
    }
    if (tid == 0) {
        out[NB]     = sqrtf(s1[0]) / 11075584.f;   // nb * 26 * 26
        out[NB + 1] = s2[0] / (float)NTOT;
    }
}

extern "C" void kernel_launch(void* const* d_in, const int* in_sizes, int n_in,
                              void* d_out, int out_size) {
    (void)in_sizes; (void)n_in; (void)out_size;
    const int*   x    = (const int*)  d_in[0];
    const int*   ei   = (const int*)  d_in[1];
    const float* emb  = (const float*)d_in[3];
    const float* cWl  = (const float*)d_in[4];
    const float* cbl  = (const float*)d_in[5];
    const float* cWr  = (const float*)d_in[6];
    const float* bng  = (const float*)d_in[7];
    const float* bnb  = (const float*)d_in[8];
    const float* bnm  = (const float*)d_in[9];
    const float* bnv  = (const float*)d_in[10];
    const float* aWl  = (const float*)d_in[11];
    const float* abl  = (const float*)d_in[12];
    const float* aWr  = (const float*)d_in[13];
    const float* linW = (const float*)d_in[14];
    const float* linb = (const float*)d_in[15];
    float* out = (float*)d_out;

    const int agg_smem  = 2 * 4 * NPG * H * 4;                 // 106496
    const int gemm_smem = (128*WPITCH + 128*APITCH) * 4;       // 102400
    cudaFuncSetAttribute(k_agg, cudaFuncAttributeMaxDynamicSharedMemorySize, agg_smem);
    cudaFuncSetAttribute(k_gemm_tc<1,0>, cudaFuncAttributeMaxDynamicSharedMemorySize, gemm_smem);
    cudaFuncSetAttribute(k_gemm_tc<0,1>, cudaFuncAttributeMaxDynamicSharedMemorySize, gemm_smem);

    k_encode<<<NTOT / 32, 128>>>(x, emb);

    for (int li = 0; li < 2; li++) {
        k_agg<<<NB / 4, 256, agg_smem>>>(ei);
        k_gemm_tc<1,0><<<NTOT / 128, 256, gemm_smem>>>(
            cWl + li*16384, cWr + li*16384, cbl + li*128,
            bng + li*128, bnb + li*128, bnm + li*128, bnv + li*128);
    }

    k_agg<<<NB / 4, 256, agg_smem>>>(ei);
    k_slog<<<2048, 256>>>(aWl, abl, aWr);
    k_pool<<<NB, 128>>>(ei);

    for (int li = 2; li < 4; li++) {
        k_pmean<<<NB * 128 / 256, 256>>>();
        k_gemm_tc<0,1><<<NB * NCL / 128, 256, gemm_smem>>>(
            cWl + li*16384, cWr + li*16384, cbl + li*128,
            bng + li*128, bnb + li*128, bnm + li*128, bnv + li*128);
    }

    k_readout<<<NB, 128>>>(linW, linb, out);
    k_reduce<<<1, 1024>>>(out);
}